// round 15
// baseline (speedup 1.0000x reference)
#include <cuda_runtime.h>
#include <cstdint>

static constexpr int   T_LEN = 4096;
static constexpr int   TC    = 64;            // steps per chunk
static constexpr int   NCH   = T_LEN / TC;    // 64
static constexpr int   ROWS  = 32;            // rows per block
static constexpr int   XD    = 6;             // x ring: spans k-2 .. k+3
static constexpr int   VD    = 2;             // v buffer ring depth
static constexpr int   SD    = 4;             // spike-bit ring depth
static constexpr int   STRW  = 68;            // padded words/row (bank-safe)
static constexpr float VTH   = 1.27f;

// Coalesced chunk copy-issue: lane (q2=lane>>4, m2=lane&15) covers row 2r+q2,
// bytes 16*m2, r=0..15. Caller commits (possibly empty) groups so wait_group
// depth accounting stays exact on the tail (round-8 invariant).
__device__ __forceinline__ void cp_chunk_issue(const float* gchunk, float* stile,
                                               int q2, int m2)
{
#pragma unroll
    for (int r = 0; r < 16; ++r) {
        const int rr = 2 * r + q2;
        unsigned sa = (unsigned)__cvta_generic_to_shared(stile + rr * STRW + 4 * m2);
        asm volatile("cp.async.ca.shared.global [%0], [%1], 16;\n"
                     :: "r"(sa), "l"(gchunk + (size_t)rr * T_LEN + 4 * m2));
    }
}

__device__ __forceinline__ void cp_commit()
{
    asm volatile("cp.async.commit_group;\n");
}

__global__ void __launch_bounds__(128)
lif_fused(const float* __restrict__ ode, const float* __restrict__ decay_p,
          float* __restrict__ v_out, float* __restrict__ s_out,
          float* __restrict__ dv_out)
{
    __shared__ float    xt[XD][ROWS][STRW];   // input chunks (ring)
    __shared__ float    vb[VD][ROWS][STRW];   // RAW u values (ring; w1 clamps)
    __shared__ unsigned sb[SD][ROWS][2];      // spike bits per chunk (2 words)
    __shared__ unsigned Wsh[ROWS][2];         // dv zero-window per row (2 words)

    const int wid  = threadIdx.x >> 5;
    const int lane = threadIdx.x & 31;
    const int q2   = lane >> 4;               // 0..1 : row parity group
    const int m2   = lane & 15;               // 0..15: 16B segment in chunk
    const int row0 = blockIdx.x * ROWS;
    const float dec = __ldg(decay_p);
    const float* xg0 = ode + (size_t)row0 * T_LEN;

    // scan state (w0): sig = unmasked sum σ_t, g1f = g_{t-1} (1.0f / 0.0f),
    // sm1..sm4 = spike masks (~0 iff spike) for steps t-1..t-4.
    float aa  = 0.0f;           // general-machine handoff (aan_63 raw)
    float sig = 0.0f;
    float g1f = 1.0f;
    int sm1 = 0, sm2 = 0, sm3 = 0, sm4 = 0, sm5 = 0;

    if (wid == 1) {
        cp_chunk_issue(xg0 + 0 * TC, &xt[0][0][0], q2, m2); cp_commit();
        cp_chunk_issue(xg0 + 1 * TC, &xt[1][0][0], q2, m2); cp_commit();
        cp_chunk_issue(xg0 + 2 * TC, &xt[2][0][0], q2, m2); cp_commit();
        asm volatile("cp.async.wait_group 2;\n" ::: "memory");  // chunk 0 ready
    }
    __syncthreads();

    for (int k = 0; k < NCH + 2; ++k) {
        // ---------------- w0: scan chunk k (lane = row) ----------------
        if (wid == 0 && k < NCH) {
            const float* xr = &xt[k % XD][lane][0];
            float*       vr = &vb[k % VD][lane][0];
            unsigned bits0 = 0u, bits1 = 0u;
            if (k == 0) {
                // general machine over whole first chunk (t=0 edge exact);
                // stores RAW pre-clamp value (w1 clamps with fminf later)
                float v = 0.0f, t2 = 0.0f; int c = 0, z = 0; bool s = false;
#pragma unroll 4
                for (int t = 0; t < TC; ++t) {
                    float x  = xr[t];
                    float xe = (z > 0) ? 0.0f : x;
                    float vd = fmaf(-dec, v, v);
                    float a  = vd + xe;
                    float b  = (c == 1) ? xe : a;
                    t2 = (c >= 2) ? VTH : b;
                    s  = t2 > VTH;
                    v  = fminf(t2, VTH);
                    vr[t] = t2;                       // raw; clamp deferred to w1
                    if (t < 32) bits0 |= s ? (1u << t) : 0u;
                    else        bits1 |= s ? (1u << (t - 32)) : 0u;
                    c = s ? (c + 1) : (c > 0 ? c - 1 : 0);
                    z = s ? (t > 0 ? 5 : z) : (z > 0 ? z - 1 : 0);
                }
                aa  = t2;                             // aan_63 raw
                sm1 = (int)bits1 >> 31;               // sm_63
                sm2 = (int)(bits1 << 1) >> 31;        // sm_62
                sm3 = (int)(bits1 << 2) >> 31;        // sm_61
                sm4 = (int)(bits1 << 3) >> 31;        // sm_60
                sm5 = (int)(bits1 << 4) >> 31;        // sm_59
            } else {
                float4 vc = *reinterpret_cast<const float4*>(xr);
                if (k == 1) {
                    // handoff: sigma_64 = (fma(-dec,aan63,aan63) + xw64) * g62
                    // xw64 masks sm_61|sm_60|sm_59 (sm_62 via g62, sm_63 squashed)
                    int xw64 = __float_as_int(vc.x) & ~(sm3 | sm4 | sm5);
                    float g62 = __int_as_float(0x3f800000 & ~sm2);
                    sig = (fmaf(-dec, aa, aa) + __int_as_float(xw64)) * g62;
                    g1f = __int_as_float(0x3f800000 & ~sm1);
                }
#pragma unroll
                for (int g4 = 0; g4 < 16; ++g4) {
                    // iteration t consumes x_{t+1}: pipeline vectors one ahead
                    float4 vn;
                    if (g4 < 15)
                        vn = *reinterpret_cast<const float4*>(xr + 4 * (g4 + 1));
                    else if (k + 1 < NCH)
                        vn = *reinterpret_cast<const float4*>(&xt[(k + 1) % XD][lane][0]);
                    else
                        vn = make_float4(0.f, 0.f, 0.f, 0.f);
                    float xs[4] = {vc.y, vc.z, vc.w, vn.x};
                    float vs[4];
#pragma unroll
                    for (int qq = 0; qq < 4; ++qq) {
                        const int t = 4 * g4 + qq;
                        float u  = sig * g1f;              // stored value (raw)
                        float vd = fmaf(-dec, sig, sig);   // chain (fma pipe)
                        int   wB = sm2 | sm3 | sm4;        // >=2-old masks only
                        int   xw = __float_as_int(xs[qq]) & ~wB;
                        float sg = vd + __int_as_float(xw);
                        float d  = VTH - u;
                        int  sm0 = __float_as_int(d) >> 31;
                        sig = sg * g1f;                    // chain FMUL (g_{t-1})
                        vs[qq] = u;
                        if (t < 32) bits0 |= (1u << t) & (unsigned)sm0;
                        else        bits1 |= (1u << (t - 32)) & (unsigned)sm0;
                        sm4 = sm3; sm3 = sm2; sm2 = sm1; sm1 = sm0;
                        g1f = __int_as_float(0x3f800000 & ~sm0);
                    }
                    *reinterpret_cast<float4*>(vr + 4 * g4) =
                        make_float4(vs[0], vs[1], vs[2], vs[3]);
                    vc = vn;
                }
            }
            sb[k % SD][lane][0] = bits0;
            sb[k % SD][lane][1] = bits1;
        }

        // ------ w1: prefetch + clamp + coalesced v store (chunk k-1) ------
        if (wid == 1) {
            if (k + 3 < NCH)
                cp_chunk_issue(xg0 + (size_t)(k + 3) * TC, &xt[(k + 3) % XD][0][0], q2, m2);
            cp_commit();   // ALWAYS commit (empty on tail) — keeps wait_group
                           // depth exact so chunk k+2 is provably complete
            const int c = k - 1;
            if (c >= 0 && c < NCH) {
                const float* vbb = &vb[c % VD][0][0];
                float* vout = v_out + (size_t)row0 * T_LEN + (size_t)c * TC;
#pragma unroll
                for (int r = 0; r < 16; ++r) {
                    const int rr = 2 * r + q2;
                    float4 v4 = *reinterpret_cast<const float4*>(vbb + rr * STRW + 4 * m2);
                    v4.x = fminf(v4.x, VTH);
                    v4.y = fminf(v4.y, VTH);
                    v4.z = fminf(v4.z, VTH);
                    v4.w = fminf(v4.w, VTH);
                    *reinterpret_cast<float4*>(vout + (size_t)rr * T_LEN + 4 * m2) = v4;
                }
            }
            asm volatile("cp.async.wait_group 1;\n" ::: "memory");
        }

        // ------ w2: coalesced s store (chunk k-1) ------
        if (wid == 2) {
            const int c = k - 1;
            if (c >= 0 && c < NCH) {
                float* sout = s_out + (size_t)row0 * T_LEN + (size_t)c * TC;
                const int h  = m2 >> 3;            // bit word for this segment
                const int tb = 4 * (m2 & 7);       // bit base within word
#pragma unroll
                for (int r = 0; r < 16; ++r) {
                    const int rr = 2 * r + q2;
                    const unsigned msk = sb[c % SD][rr][h];
                    float sf[4];
#pragma unroll
                    for (int j = 0; j < 4; ++j)
                        sf[j] = __int_as_float(
                            ((int)(msk << (31 - (tb + j))) >> 31) & 0x3f800000);
                    *reinterpret_cast<float4*>(sout + (size_t)rr * T_LEN + 4 * m2) =
                        make_float4(sf[0], sf[1], sf[2], sf[3]);
                }
            }
        }

        // ------ w3: coalesced dv (chunk k-2) ------
        if (wid == 3) {
            const int c = k - 2;
            if (c >= 0 && c < NCH) {
                // phase A: lane computes zero-window words for its own row
                const unsigned* sbc = sb[c % SD][lane];
#pragma unroll
                for (int h = 0; h < 2; ++h) {
                    unsigned mm, mp, mn;
                    if (h == 0) {
                        mm = sbc[0];
                        mp = (c > 0) ? sb[(c - 1) % SD][lane][1] : 0u;
                        mn = sbc[1] & 1u;
                        if (c == 0) mm &= ~1u;   // spike at t=0 zeroes nothing
                    } else {
                        mm = sbc[1];
                        mp = sbc[0];
                        if (c == 0) mp &= ~1u;
                        mn = (c + 1 < NCH) ? (sb[(c + 1) % SD][lane][0] & 1u) : 0u;
                    }
                    unsigned long long W = ((unsigned long long)mm << 5) | (mp >> 27)
                                         | ((unsigned long long)mn << 37);
                    W |= W >> 1; W |= W >> 2; W |= W >> 3;
                    Wsh[lane][h] = (unsigned)W;  // bit t set -> zero dv[..+32h+t]
                }
                __syncwarp();
                // phase B: coalesced store pass
                const float* xb = &xt[c % XD][0][0];
                float* dout = dv_out + (size_t)row0 * T_LEN + (size_t)c * TC;
                const int h  = m2 >> 3;
                const int tb = 4 * (m2 & 7);
#pragma unroll
                for (int r = 0; r < 16; ++r) {
                    const int rr = 2 * r + q2;
                    const unsigned V = Wsh[rr][h];
                    float4 x4 = *reinterpret_cast<const float4*>(xb + rr * STRW + 4 * m2);
                    int xw[4] = {__float_as_int(x4.x), __float_as_int(x4.y),
                                 __float_as_int(x4.z), __float_as_int(x4.w)};
                    float rv[4];
#pragma unroll
                    for (int j = 0; j < 4; ++j) {
                        int mskb = (int)(V << (31 - (tb + j))) >> 31;
                        rv[j] = __int_as_float(xw[j] & ~mskb);
                    }
                    *reinterpret_cast<float4*>(dout + (size_t)rr * T_LEN + 4 * m2) =
                        make_float4(rv[0], rv[1], rv[2], rv[3]);
                }
                __syncwarp();   // protect Wsh before next iteration's phase A
            }
        }

        __syncthreads();
    }
}

extern "C" void kernel_launch(void* const* d_in, const int* in_sizes, int n_in,
                              void* d_out, int out_size)
{
    const float* ode     = (const float*)d_in[0];
    const float* decay_p = (const float*)d_in[1];
    float*       out     = (float*)d_out;

    const int BT = in_sizes[0];
    const int B  = BT / T_LEN;

    float* v_out  = out;
    float* s_out  = out + (size_t)BT;
    float* dv_out = out + (size_t)2 * BT;

    lif_fused<<<B / ROWS, 128>>>(ode, decay_p, v_out, s_out, dv_out);
}